// round 1
// baseline (speedup 1.0000x reference)
#include <cuda_runtime.h>

// ---------------------------------------------------------------------------
// LogicMachine (breadth=2, minmax, exclude_self, sigmoid), 3 layers.
// B=4, n=256, O=128. Layer dims: L0 in = (32,64,64); L1/L2 in = (128,128,128).
//
// o2[b,i,j] = sigmoid( P[b,i] + Q[b,j] + f2[b,i,j]·Wb + f2[b,j,i]·Wd )
//   with P = f1·Wa + b2, Q = f1·Wc   (Wa/Wb/Wc/Wd = row-slices of W2)
// ---------------------------------------------------------------------------

#define BD 4
#define NN 256
#define OO 128

// Ping-pong inter-layer buffers (static __device__ — no allocations allowed).
__device__ float g_f2a[(size_t)BD * NN * NN * 128];
__device__ float g_f2b[(size_t)BD * NN * NN * 128];
__device__ float g_f1a[BD * NN * 128];
__device__ float g_f1b[BD * NN * 128];
__device__ float g_f0a[BD * 128];
__device__ float g_f0b[BD * 128];
__device__ float g_r1[BD * 2 * 128];
__device__ float g_r2[BD * NN * 2 * 128];
__device__ float g_P[BD * NN * OO];
__device__ float g_Q[BD * NN * OO];

__device__ __forceinline__ float sigmoidf_(float x) {
    return 1.0f / (1.0f + __expf(-x));
}

// Packed f32x2 helpers (sm_100+ PTX).
__device__ __forceinline__ unsigned long long pk2(float x) {
    unsigned long long r;
    asm("mov.b64 %0, {%1, %1};" : "=l"(r) : "f"(x));
    return r;
}
__device__ __forceinline__ void fma2(unsigned long long& d,
                                     unsigned long long a,
                                     unsigned long long b) {
    asm("fma.rn.f32x2 %0, %1, %2, %0;" : "+l"(d) : "l"(a), "l"(b));
}
__device__ __forceinline__ float2 up2(unsigned long long v) {
    float2 r;
    asm("mov.b64 {%0, %1}, %2;" : "=f"(r.x), "=f"(r.y) : "l"(v));
    return r;
}

// ---------------------------------------------------------------------------
// Reductions
// ---------------------------------------------------------------------------

// r1[b, 0:d1] = max_i f1[b,i,:] ; r1[b, d1:2d1] = min_i f1[b,i,:]
__global__ void k_reduce1(const float* __restrict__ f1, float* __restrict__ r1, int d1) {
    int b = blockIdx.x;
    int k = threadIdx.x;
    if (k >= d1) return;
    const float* p = f1 + (size_t)b * NN * d1 + k;
    float mx = -1e30f, mn = 1e30f;
    for (int i = 0; i < NN; i++) {
        float v = p[(size_t)i * d1];
        mx = fmaxf(mx, v);
        mn = fminf(mn, v);
    }
    r1[b * 2 * d1 + k] = mx;
    r1[b * 2 * d1 + d1 + k] = mn;
}

// r2[b,i, 0:d2] = max_j (diag->0) f2[b,i,j,:] ; r2[b,i, d2:2d2] = min_j (diag->1)
__global__ void k_reduce2(const float* __restrict__ f2, float* __restrict__ r2, int d2) {
    int bi = blockIdx.x;               // b*NN + i
    int i = bi % NN;
    int k = threadIdx.x;
    if (k >= d2) return;
    const float* p = f2 + (size_t)bi * NN * d2 + k;
    float mx = -1e30f, mn = 1e30f;
    for (int j = 0; j < NN; j++) {
        float v = p[(size_t)j * d2];
        float vm = (j == i) ? 0.0f : v;
        float vn = (j == i) ? 1.0f : v;
        mx = fmaxf(mx, vm);
        mn = fminf(mn, vn);
    }
    r2[(size_t)bi * 2 * d2 + k] = mx;
    r2[(size_t)bi * 2 * d2 + d2 + k] = mn;
}

// ---------------------------------------------------------------------------
// Order 0: o0[b,:] = sigmoid(cat(f0[b], r1[b]) @ W0 + b0)
// ---------------------------------------------------------------------------
__global__ void k_ord0(const float* __restrict__ f0, const float* __restrict__ r1,
                       const float* __restrict__ W, const float* __restrict__ bias,
                       float* __restrict__ out, int d0, int d1) {
    __shared__ float sg[384];
    int b = blockIdx.x, t = threadIdx.x;
    for (int idx = t; idx < d0; idx += blockDim.x) sg[idx] = f0[b * d0 + idx];
    for (int idx = t; idx < 2 * d1; idx += blockDim.x) sg[d0 + idx] = r1[b * 2 * d1 + idx];
    __syncthreads();
    int K = d0 + 2 * d1;
    float acc = bias[t];
    for (int k = 0; k < K; k++) acc += sg[k] * W[k * OO + t];
    out[b * OO + t] = sigmoidf_(acc);
}

// ---------------------------------------------------------------------------
// Order 1: o1[b,i,:] = sigmoid(cat(f0[b], f1[b,i], r2[b,i]) @ W1 + b1)
// ---------------------------------------------------------------------------
__global__ void k_ord1(const float* __restrict__ f0, const float* __restrict__ f1,
                       const float* __restrict__ r2,
                       const float* __restrict__ W, const float* __restrict__ bias,
                       float* __restrict__ out, int d0, int d1, int d2) {
    __shared__ float sg[512];
    int bi = blockIdx.x;
    int b = bi / NN;
    int t = threadIdx.x;
    for (int idx = t; idx < d0; idx += 128) sg[idx] = f0[b * d0 + idx];
    for (int idx = t; idx < d1; idx += 128) sg[d0 + idx] = f1[(size_t)bi * d1 + idx];
    for (int idx = t; idx < 2 * d2; idx += 128) sg[d0 + d1 + idx] = r2[(size_t)bi * 2 * d2 + idx];
    __syncthreads();
    int K = d0 + d1 + 2 * d2;
    float acc = bias[t];
#pragma unroll 4
    for (int k = 0; k < K; k++) acc += sg[k] * W[k * OO + t];
    out[(size_t)bi * OO + t] = sigmoidf_(acc);
}

// ---------------------------------------------------------------------------
// P[b,i,:] = f1[b,i]·Wa + b2 ; Q[b,i,:] = f1[b,i]·Wc
//   Wa = W2 rows [0,d1), Wc = W2 rows [d1+d2, 2d1+d2)
// ---------------------------------------------------------------------------
__global__ void k_pq(const float* __restrict__ f1, const float* __restrict__ W2,
                     const float* __restrict__ b2,
                     float* __restrict__ P, float* __restrict__ Q, int d1, int d2) {
    __shared__ float sf[128];
    int bi = blockIdx.x;
    int t = threadIdx.x;
    for (int idx = t; idx < d1; idx += 128) sf[idx] = f1[(size_t)bi * d1 + idx];
    __syncthreads();
    const float* Wa = W2;
    const float* Wc = W2 + (size_t)(d1 + d2) * OO;
    float p = b2[t], q = 0.0f;
#pragma unroll 4
    for (int k = 0; k < d1; k++) {
        float x = sf[k];
        p += x * Wa[k * OO + t];
        q += x * Wc[k * OO + t];
    }
    P[(size_t)bi * OO + t] = p;
    Q[(size_t)bi * OO + t] = q;
}

// ---------------------------------------------------------------------------
// Order 2 (the big one). One block per (b,i). 256 threads.
// Tile of 64 j-elements; warp eg owns elements eg*8..eg*8+7; lane owns 4
// output cols (ob..ob+3). acc as packed f32x2 pairs (fma.rn.f32x2).
// smem: Wb[D2][128], Wd[D2][128], Xa[64][D2], Xb[64][D2], P[128]
// ---------------------------------------------------------------------------
template <int D2>
__device__ __forceinline__ void mac_pass(const float* __restrict__ sW,
                                         const float* __restrict__ sX,
                                         int eg, int ob,
                                         unsigned long long (&acc)[8][2]) {
#pragma unroll 1
    for (int k = 0; k < D2; k += 4) {
        ulonglong2 w0 = *(const ulonglong2*)(sW + (k + 0) * OO + ob);
        ulonglong2 w1 = *(const ulonglong2*)(sW + (k + 1) * OO + ob);
        ulonglong2 w2 = *(const ulonglong2*)(sW + (k + 2) * OO + ob);
        ulonglong2 w3 = *(const ulonglong2*)(sW + (k + 3) * OO + ob);
#pragma unroll
        for (int e = 0; e < 8; e++) {
            float4 xv = *(const float4*)(sX + (eg * 8 + e) * D2 + k);
            unsigned long long xx;
            xx = pk2(xv.x); fma2(acc[e][0], xx, w0.x); fma2(acc[e][1], xx, w0.y);
            xx = pk2(xv.y); fma2(acc[e][0], xx, w1.x); fma2(acc[e][1], xx, w1.y);
            xx = pk2(xv.z); fma2(acc[e][0], xx, w2.x); fma2(acc[e][1], xx, w2.y);
            xx = pk2(xv.w); fma2(acc[e][0], xx, w3.x); fma2(acc[e][1], xx, w3.y);
        }
    }
}

template <int D2>
__global__ __launch_bounds__(256) void k_ord2(
    const float* __restrict__ f2,
    const float* __restrict__ Wb, const float* __restrict__ Wd,
    const float* __restrict__ P, const float* __restrict__ Q,
    float* __restrict__ out) {
    extern __shared__ float sm[];
    float* sWb = sm;
    float* sWd = sWb + D2 * OO;
    float* sXa = sWd + D2 * OO;
    float* sXb = sXa + 64 * D2;
    float* sP  = sXb + 64 * D2;

    int t = threadIdx.x;
    int bi = blockIdx.x;           // b*NN + i
    int b = bi / NN, i = bi % NN;

    // Load weights (contiguous row blocks of W2) + P row.
    for (int idx = t; idx < D2 * OO / 4; idx += 256) {
        ((float4*)sWb)[idx] = ((const float4*)Wb)[idx];
        ((float4*)sWd)[idx] = ((const float4*)Wd)[idx];
    }
    for (int idx = t; idx < OO; idx += 256) sP[idx] = P[(size_t)bi * OO + idx];

    int lane = t & 31, eg = t >> 5;
    int ob = lane * 4;
    const float* f2row = f2 + (size_t)bi * NN * D2;   // f2[b,i,:,:]

    for (int jt = 0; jt < NN; jt += 64) {
        __syncthreads();
        // Xa = f2[b,i,jt..jt+63,:]  (contiguous)
        {
            const float4* src = (const float4*)(f2row + (size_t)jt * D2);
            for (int idx = t; idx < 64 * D2 / 4; idx += 256) ((float4*)sXa)[idx] = src[idx];
        }
        // Xb[r] = f2[b,jt+r,i,:]  (gathered rows)
        {
            int r = t >> 2, c = t & 3;
            const float4* src = (const float4*)(f2 + ((size_t)(b * NN + jt + r) * NN + i) * D2);
            float4* dst = (float4*)(sXb + r * D2);
#pragma unroll
            for (int cc = c; cc < D2 / 4; cc += 4) dst[cc] = src[cc];
        }
        __syncthreads();

        unsigned long long acc[8][2];
#pragma unroll
        for (int e = 0; e < 8; e++) { acc[e][0] = 0ull; acc[e][1] = 0ull; }

        mac_pass<D2>(sWb, sXa, eg, ob, acc);
        mac_pass<D2>(sWd, sXb, eg, ob, acc);

#pragma unroll
        for (int e = 0; e < 8; e++) {
            int j = jt + eg * 8 + e;
            float4 q = *(const float4*)(Q + ((size_t)(b * NN) + j) * OO + ob);
            float2 a0 = up2(acc[e][0]);
            float2 a1 = up2(acc[e][1]);
            float4 r;
            r.x = sigmoidf_(sP[ob + 0] + q.x + a0.x);
            r.y = sigmoidf_(sP[ob + 1] + q.y + a0.y);
            r.z = sigmoidf_(sP[ob + 2] + q.z + a1.x);
            r.w = sigmoidf_(sP[ob + 3] + q.w + a1.y);
            *(float4*)(out + ((size_t)bi * NN + j) * OO + ob) = r;
        }
    }
}

// ---------------------------------------------------------------------------
// Host side
// ---------------------------------------------------------------------------

static inline size_t smem_ord2(int d2) {
    return (size_t)(2 * d2 * OO + 2 * 64 * d2 + OO) * sizeof(float);
}

extern "C" void kernel_launch(void* const* d_in, const int* in_sizes, int n_in,
                              void* d_out, int out_size) {
    const float* x0 = (const float*)d_in[0];
    const float* x1 = (const float*)d_in[1];
    const float* x2 = (const float*)d_in[2];
    const float* Wt[3][3];
    const float* bt[3][3];
    for (int l = 0; l < 3; l++)
        for (int o = 0; o < 3; o++) {
            Wt[l][o] = (const float*)d_in[3 + l * 6 + o * 2];
            bt[l][o] = (const float*)d_in[3 + l * 6 + o * 2 + 1];
        }

    float *f2a, *f2b, *f1a, *f1b, *f0a, *f0b, *r1, *r2, *P, *Q;
    cudaGetSymbolAddress((void**)&f2a, g_f2a);
    cudaGetSymbolAddress((void**)&f2b, g_f2b);
    cudaGetSymbolAddress((void**)&f1a, g_f1a);
    cudaGetSymbolAddress((void**)&f1b, g_f1b);
    cudaGetSymbolAddress((void**)&f0a, g_f0a);
    cudaGetSymbolAddress((void**)&f0b, g_f0b);
    cudaGetSymbolAddress((void**)&r1, g_r1);
    cudaGetSymbolAddress((void**)&r2, g_r2);
    cudaGetSymbolAddress((void**)&P, g_P);
    cudaGetSymbolAddress((void**)&Q, g_Q);

    float* out = (float*)d_out;
    float* o0_f = out;                                   // [4,128]
    float* o1_f = out + BD * OO;                         // [4,256,128]
    float* o2_f = out + BD * OO + (size_t)BD * NN * OO;  // [4,256,256,128]

    cudaFuncSetAttribute(k_ord2<64>, cudaFuncAttributeMaxDynamicSharedMemorySize,
                         (int)smem_ord2(64));
    cudaFuncSetAttribute(k_ord2<128>, cudaFuncAttributeMaxDynamicSharedMemorySize,
                         (int)smem_ord2(128));

    struct L {
        const float *f0, *f1, *f2;
        float *o0, *o1, *o2;
        int d0, d1, d2;
    };
    L Ls[3] = {
        { x0,  x1,  x2,  f0a,  f1a,  f2a,  32,  64,  64 },
        { f0a, f1a, f2a, f0b,  f1b,  f2b,  128, 128, 128 },
        { f0b, f1b, f2b, o0_f, o1_f, o2_f, 128, 128, 128 },
    };

    for (int l = 0; l < 3; l++) {
        const L& a = Ls[l];
        k_reduce1<<<BD, 128>>>(a.f1, r1, a.d1);
        k_reduce2<<<BD * NN, 128>>>(a.f2, r2, a.d2);
        k_ord0<<<BD, 128>>>(a.f0, r1, Wt[l][0], bt[l][0], a.o0, a.d0, a.d1);
        k_ord1<<<BD * NN, 128>>>(a.f0, a.f1, r2, Wt[l][1], bt[l][1], a.o1,
                                 a.d0, a.d1, a.d2);
        k_pq<<<BD * NN, 128>>>(a.f1, Wt[l][2], bt[l][2], P, Q, a.d1, a.d2);
        const float* Wb = Wt[l][2] + (size_t)a.d1 * OO;
        const float* Wd = Wt[l][2] + (size_t)(2 * a.d1 + a.d2) * OO;
        if (a.d2 == 64)
            k_ord2<64><<<BD * NN, 256, smem_ord2(64)>>>(a.f2, Wb, Wd, P, Q, a.o2);
        else
            k_ord2<128><<<BD * NN, 256, smem_ord2(128)>>>(a.f2, Wb, Wd, P, Q, a.o2);
    }
}